// round 13
// baseline (speedup 1.0000x reference)
#include <cuda_runtime.h>
#include <cuda_bf16.h>
#include <cstdint>
#include <cstddef>
#include <math.h>

// Problem constants
#define S_DIM 128
#define L_DIM 512
#define D_DIM 256
#define H_DIM 8
#define C_DIM 32
#define HC    256
#define ROWS  65536

// ---------------- scratch (device globals; allocation-free) ----------------
// g_x, g_q, g_k, g_v, g_wT, g_o hold tf32-bit patterns (as float storage).
__device__ float g_x[(size_t)ROWS * D_DIM];
__device__ float g_q[(size_t)ROWS * HC];
__device__ float g_k[(size_t)ROWS * HC];
__device__ float g_v[(size_t)ROWS * HC];
__device__ float g_gate[(size_t)ROWS * HC];   // fp32 (sigmoid output)
__device__ float g_o[(size_t)ROWS * HC];
__device__ float g_wT[5 * 256 * 256];         // transposed weights, tf32 bits; wq pre-scaled

__device__ __forceinline__ uint32_t f2tf(float f) {
    uint32_t u;
    asm("cvt.rna.tf32.f32 %0, %1;" : "=r"(u) : "f"(f));
    return u;
}
__device__ __forceinline__ uint32_t smem_u32(const void* p) {
    uint32_t a;
    asm("{ .reg .u64 t; cvta.to.shared.u64 t, %1; cvt.u32.u64 %0, t; }" : "=r"(a) : "l"(p));
    return a;
}
__device__ __forceinline__ void cp16(uint32_t dst, const void* src) {
    asm volatile("cp.async.cg.shared.global [%0], [%1], 16;" :: "r"(dst), "l"(src) : "memory");
}
#define CP_COMMIT() asm volatile("cp.async.commit_group;" ::: "memory")
#define CP_WAIT(n)  asm volatile("cp.async.wait_group %0;" :: "n"(n) : "memory")
__device__ __forceinline__ void ldsm4(uint32_t& r0, uint32_t& r1, uint32_t& r2, uint32_t& r3,
                                      uint32_t addr) {
    asm volatile("ldmatrix.sync.aligned.m8n8.x4.shared.b16 {%0,%1,%2,%3}, [%4];"
                 : "=r"(r0), "=r"(r1), "=r"(r2), "=r"(r3) : "r"(addr));
}
__device__ __forceinline__ void mma8(float* c, const uint32_t* a, uint32_t b0, uint32_t b1) {
    asm volatile(
        "mma.sync.aligned.m16n8k8.row.col.f32.tf32.tf32.f32 "
        "{%0,%1,%2,%3}, {%4,%5,%6,%7}, {%8,%9}, {%0,%1,%2,%3};"
        : "+f"(c[0]), "+f"(c[1]), "+f"(c[2]), "+f"(c[3])
        : "r"(a[0]), "r"(a[1]), "r"(a[2]), "r"(a[3]), "r"(b0), "r"(b1));
}

// ---------------- LayerNorm: one warp per row of 256, outputs tf32 bits ----------------
__global__ void __launch_bounds__(256) ln_kernel(const float* __restrict__ in,
                                                 const float* __restrict__ sc,
                                                 const float* __restrict__ bi) {
    int row  = blockIdx.x * blockDim.y + threadIdx.y;
    int lane = threadIdx.x;
    const float4* p = (const float4*)(in + (size_t)row * D_DIM);
    float4 a = p[lane];
    float4 b = p[lane + 32];
    float s  = a.x + a.y + a.z + a.w + b.x + b.y + b.z + b.w;
    float s2 = a.x*a.x + a.y*a.y + a.z*a.z + a.w*a.w
             + b.x*b.x + b.y*b.y + b.z*b.z + b.w*b.w;
    #pragma unroll
    for (int off = 16; off > 0; off >>= 1) {
        s  += __shfl_xor_sync(0xFFFFFFFF, s,  off);
        s2 += __shfl_xor_sync(0xFFFFFFFF, s2, off);
    }
    float mean = s * (1.0f / 256.0f);
    float var  = s2 * (1.0f / 256.0f) - mean * mean;
    float inv  = rsqrtf(var + 1e-5f);

    const float4* scp = (const float4*)sc;
    const float4* bip = (const float4*)bi;
    float4 sa = scp[lane], sb = scp[lane + 32];
    float4 ba = bip[lane], bb = bip[lane + 32];
    uint4 oa, ob;
    oa.x = f2tf((a.x - mean) * inv * sa.x + ba.x);
    oa.y = f2tf((a.y - mean) * inv * sa.y + ba.y);
    oa.z = f2tf((a.z - mean) * inv * sa.z + ba.z);
    oa.w = f2tf((a.w - mean) * inv * sa.w + ba.w);
    ob.x = f2tf((b.x - mean) * inv * sb.x + bb.x);
    ob.y = f2tf((b.y - mean) * inv * sb.y + bb.y);
    ob.z = f2tf((b.z - mean) * inv * sb.z + bb.z);
    ob.w = f2tf((b.w - mean) * inv * sb.w + bb.w);
    uint4* q = (uint4*)(g_x + (size_t)row * D_DIM);
    q[lane]      = oa;
    q[lane + 32] = ob;
}

// ---------------- weight transpose -> tf32 bits; wq pre-scaled by 1/sqrt(C) ----------------
__global__ void __launch_bounds__(256) transpose_w(const float* __restrict__ wq,
                                                   const float* __restrict__ wk,
                                                   const float* __restrict__ wv,
                                                   const float* __restrict__ wg,
                                                   const float* __restrict__ wo) {
    const float* srcs[5] = {wq, wk, wv, wg, wo};
    const float* src = srcs[blockIdx.z];
    float* dst = g_wT + (size_t)blockIdx.z * 65536;
    float mul = (blockIdx.z == 0) ? 0.17677669529663687f : 1.0f;
    __shared__ float t[32][33];
    int tx = threadIdx.x, ty = threadIdx.y;
    int x  = blockIdx.x * 32 + tx;
    int y0 = blockIdx.y * 32;
    #pragma unroll
    for (int j = 0; j < 32; j += 8)
        t[ty + j][tx] = src[(size_t)(y0 + ty + j) * 256 + x];
    __syncthreads();
    int nx = blockIdx.y * 32 + tx;
    #pragma unroll
    for (int j = 0; j < 32; j += 8)
        dst[(size_t)(blockIdx.x * 32 + ty + j) * 256 + nx] =
            __uint_as_float(f2tf(t[tx][ty + j] * mul));
}

// ---------------- TF32 GEMM: 128x128 tile, 256 threads, cp.async + ldmatrix ----------------
#define BKW 20
#define BUFW (128 * BKW)

__device__ __forceinline__ void gemm_ldsm_tile(const float* __restrict__ A,
                                               const float* __restrict__ Bt,
                                               int row0, int col0,
                                               float* __restrict__ Cout, int ldc,
                                               const float* __restrict__ bias,
                                               bool do_sig, bool tf32_out) {
    __shared__ uint32_t As[2 * BUFW];
    __shared__ uint32_t Bs[2 * BUFW];

    int tid  = threadIdx.x;
    int lane = tid & 31;
    int wid  = tid >> 5;
    int wm   = wid & 1;
    int wn   = wid >> 1;
    int la3  = lane & 3;
    int lr   = lane >> 2;

    uint32_t sA = smem_u32(As);
    uint32_t sB = smem_u32(Bs);

    int tileid = lane >> 3;
    int lrow   = lane & 7;
    uint32_t aBase = (((uint32_t)(wm * 64 + (tileid & 1) * 8 + lrow)) * BKW
                      + (uint32_t)(tileid >> 1) * 4) * 4;
    uint32_t bBase = (((uint32_t)(wn * 32 + (tileid & 1) * 8 + lrow)) * BKW
                      + (uint32_t)(tileid >> 1) * 4) * 4;

    float acc[4][4][4];
    #pragma unroll
    for (int mi = 0; mi < 4; mi++)
        #pragma unroll
        for (int ni = 0; ni < 4; ni++)
            #pragma unroll
            for (int q = 0; q < 4; q++) acc[mi][ni][q] = 0.0f;

    int m0 = tid >> 2;                 // rows for this thread: m0, m0+64
    int kq = (tid & 3) * 4;

    const float* aRow0 = A  + (size_t)(row0 + m0) * 256 + kq;
    const float* aRow1 = A  + (size_t)(row0 + m0 + 64) * 256 + kq;
    const float* bRow0 = Bt + (size_t)(col0 + m0) * 256 + kq;
    const float* bRow1 = Bt + (size_t)(col0 + m0 + 64) * 256 + kq;
    uint32_t sa0 = sA + (uint32_t)(m0 * BKW + kq) * 4;
    uint32_t sa1 = sA + (uint32_t)((m0 + 64) * BKW + kq) * 4;
    uint32_t sb0 = sB + (uint32_t)(m0 * BKW + kq) * 4;
    uint32_t sb1 = sB + (uint32_t)((m0 + 64) * BKW + kq) * 4;

    // prologue: chunk 0 into buf 0
    cp16(sa0, aRow0);
    cp16(sa1, aRow1);
    cp16(sb0, bRow0);
    cp16(sb1, bRow1);
    CP_COMMIT();

    for (int c = 0; c < 16; c++) {
        if (c < 15) {
            uint32_t off = (uint32_t)((c + 1) & 1) * (BUFW * 4);
            cp16(sa0 + off, aRow0 + (c + 1) * 16);
            cp16(sa1 + off, aRow1 + (c + 1) * 16);
            cp16(sb0 + off, bRow0 + (c + 1) * 16);
            cp16(sb1 + off, bRow1 + (c + 1) * 16);
            CP_COMMIT();
            CP_WAIT(1);
        } else {
            CP_WAIT(0);
        }
        __syncthreads();

        uint32_t aOff = sA + (uint32_t)(c & 1) * (BUFW * 4) + aBase;
        uint32_t bOff = sB + (uint32_t)(c & 1) * (BUFW * 4) + bBase;
        #pragma unroll
        for (int kk = 0; kk < 16; kk += 8) {
            uint32_t af[4][4];
            #pragma unroll
            for (int mi = 0; mi < 4; mi++)
                ldsm4(af[mi][0], af[mi][1], af[mi][2], af[mi][3],
                      aOff + (uint32_t)(mi * 16 * BKW + kk) * 4);
            uint32_t bf[4][2];
            #pragma unroll
            for (int j = 0; j < 2; j++) {
                uint32_t r0, r1, r2, r3;
                ldsm4(r0, r1, r2, r3, bOff + (uint32_t)(j * 16 * BKW + kk) * 4);
                bf[2 * j + 0][0] = r0; bf[2 * j + 1][0] = r1;
                bf[2 * j + 0][1] = r2; bf[2 * j + 1][1] = r3;
            }
            #pragma unroll
            for (int mi = 0; mi < 4; mi++)
                #pragma unroll
                for (int ni = 0; ni < 4; ni++)
                    mma8(acc[mi][ni], af[mi], bf[ni][0], bf[ni][1]);
        }
        __syncthreads();   // all warps done reading buf[c&1] before it's rewritten
    }

    #pragma unroll
    for (int mi = 0; mi < 4; mi++) {
        #pragma unroll
        for (int half = 0; half < 2; half++) {
            int rg = row0 + wm * 64 + mi * 16 + lr + half * 8;
            #pragma unroll
            for (int ni = 0; ni < 4; ni++) {
                int cg = col0 + wn * 32 + ni * 8 + la3 * 2;
                float v0 = acc[mi][ni][half * 2 + 0];
                float v1 = acc[mi][ni][half * 2 + 1];
                if (bias) { v0 += bias[cg]; v1 += bias[cg + 1]; }
                if (do_sig) {
                    v0 = 1.0f / (1.0f + __expf(-v0));
                    v1 = 1.0f / (1.0f + __expf(-v1));
                }
                if (tf32_out) {
                    v0 = __uint_as_float(f2tf(v0));
                    v1 = __uint_as_float(f2tf(v1));
                }
                *(float2*)(Cout + (size_t)rg * ldc + cg) = make_float2(v0, v1);
            }
        }
    }
}

// grid: (8, 512) — N-block fastest so the 8 CTAs sharing an A tile are concurrent
__global__ void __launch_bounds__(256, 2) proj_kernel(const float* __restrict__ bg) {
    int nblk = blockIdx.x;              // 0..7
    int row0 = blockIdx.y * 128;
    int wsel = nblk >> 1;
    int colW = (nblk & 1) * 128;
    const float* Bt = g_wT + (size_t)wsel * 65536;
    float* out;
    const float* bias = nullptr;
    bool sig = false, tf = true;
    switch (wsel) {
        case 0: out = g_q; break;
        case 1: out = g_k; break;
        case 2: out = g_v; break;
        default: out = g_gate; bias = bg; sig = true; tf = false; break;
    }
    gemm_ldsm_tile(g_x, Bt, row0, colW, out, HC, bias, sig, tf);
}

// grid: (2, 512)
__global__ void __launch_bounds__(256, 2) outproj_kernel(const float* __restrict__ bo,
                                                         float* __restrict__ out) {
    int colW = blockIdx.x * 128;
    int row0 = blockIdx.y * 128;
    gemm_ldsm_tile(g_o, g_wT + 4 * 65536, row0, colW, out, D_DIM, bo, false, false);
}

// ---------------- attention: cp.async K/V staging, Q direct from gmem ----------------
#define ATW 36
#define ATTN_SMEM (2 * 128 * ATW * 4)   // 36864 B -> 6 CTAs/SM

__global__ void __launch_bounds__(128) attn_tc_kernel() {
    extern __shared__ uint32_t shm[];
    uint32_t* Ks = shm;
    uint32_t* Vs = shm + 128 * ATW;

    int l = blockIdx.x >> 3;
    int h = blockIdx.x & 7;
    int tid  = threadIdx.x;
    int lane = tid & 31;
    int wid  = tid >> 5;
    int la3  = lane & 3;
    int lr   = lane >> 2;

    const size_t srow = (size_t)L_DIM * HC;
    const size_t base = (size_t)l * HC + (size_t)h * C_DIM;

    uint32_t kA = smem_u32(Ks);
    uint32_t vA = smem_u32(Vs);

    // ---- stage K, V via cp.async ----
    {
        int tloc = tid >> 3;
        int cq   = (tid & 7) * 4;
        #pragma unroll
        for (int p = 0; p < 8; p++) {
            int r = p * 16 + tloc;
            size_t gi = base + (size_t)r * srow + cq;
            uint32_t so = (uint32_t)(r * ATW + cq) * 4;
            cp16(kA + so, g_k + gi);
            cp16(vA + so, g_v + gi);
        }
    }
    CP_COMMIT();

    // ---- Q fragments straight from gmem (tf32 bits, pre-scaled) ----
    uint32_t af1[4][2][4];
    {
        const uint32_t* qg = (const uint32_t*)g_q;
        #pragma unroll
        for (int mi = 0; mi < 2; mi++) {
            int r = wid * 32 + mi * 16 + lr;
            const uint32_t* q0 = qg + base + (size_t)r * srow;
            const uint32_t* q8 = qg + base + (size_t)(r + 8) * srow;
            #pragma unroll
            for (int kk = 0; kk < 4; kk++) {
                int c = kk * 8 + la3;
                af1[kk][mi][0] = q0[c];
                af1[kk][mi][1] = q8[c];
                af1[kk][mi][2] = q0[c + 4];
                af1[kk][mi][3] = q8[c + 4];
            }
        }
    }

    CP_WAIT(0);
    __syncthreads();

    float acc2[2][4][4];
    #pragma unroll
    for (int mi = 0; mi < 2; mi++)
        #pragma unroll
        for (int ni = 0; ni < 4; ni++)
            #pragma unroll
            for (int q = 0; q < 4; q++) acc2[mi][ni][q] = 0.0f;
    float rsum[2][2] = {{0.f, 0.f}, {0.f, 0.f}};

    int srcA = (lane & 28) | (la3 >> 1);
    int srcB = srcA | 2;
    int sel  = la3 & 1;

    for (int ni = 0; ni < 16; ni++) {
        float s[2][4];
        #pragma unroll
        for (int mi = 0; mi < 2; mi++)
            #pragma unroll
            for (int q = 0; q < 4; q++) s[mi][q] = 0.0f;

        #pragma unroll
        for (int kk = 0; kk < 4; kk++) {
            int t = ni * 8 + lr;
            int c = kk * 8 + la3;
            uint32_t b0 = Ks[t * ATW + c];
            uint32_t b1 = Ks[t * ATW + c + 4];
            mma8(s[0], af1[kk][0], b0, b1);
            mma8(s[1], af1[kk][1], b0, b1);
        }

        float e[2][4];
        #pragma unroll
        for (int mi = 0; mi < 2; mi++)
            #pragma unroll
            for (int q = 0; q < 4; q++) {
                float ev = __expf(s[mi][q]);
                e[mi][q] = ev;
                rsum[mi][q >> 1] += ev;
            }

        uint32_t a2[2][4];
        #pragma unroll
        for (int mi = 0; mi < 2; mi++) {
            float v0 = __shfl_sync(0xFFFFFFFF, e[mi][0], srcA);
            float v1 = __shfl_sync(0xFFFFFFFF, e[mi][1], srcA);
            float v2 = __shfl_sync(0xFFFFFFFF, e[mi][2], srcA);
            float v3 = __shfl_sync(0xFFFFFFFF, e[mi][3], srcA);
            float w0 = __shfl_sync(0xFFFFFFFF, e[mi][0], srcB);
            float w1 = __shfl_sync(0xFFFFFFFF, e[mi][1], srcB);
            float w2 = __shfl_sync(0xFFFFFFFF, e[mi][2], srcB);
            float w3 = __shfl_sync(0xFFFFFFFF, e[mi][3], srcB);
            a2[mi][0] = f2tf(sel ? v1 : v0);
            a2[mi][1] = f2tf(sel ? v3 : v2);
            a2[mi][2] = f2tf(sel ? w1 : w0);
            a2[mi][3] = f2tf(sel ? w3 : w2);
        }

        #pragma unroll
        for (int ni2 = 0; ni2 < 4; ni2++) {
            int t = ni * 8 + la3;
            uint32_t b0 = Vs[t * ATW + ni2 * 8 + lr];
            uint32_t b1 = Vs[(t + 4) * ATW + ni2 * 8 + lr];
            mma8(acc2[0][ni2], a2[0], b0, b1);
            mma8(acc2[1][ni2], a2[1], b0, b1);
        }
    }

    #pragma unroll
    for (int mi = 0; mi < 2; mi++)
        #pragma unroll
        for (int hf = 0; hf < 2; hf++) {
            float v = rsum[mi][hf];
            v += __shfl_xor_sync(0xFFFFFFFF, v, 1);
            v += __shfl_xor_sync(0xFFFFFFFF, v, 2);
            rsum[mi][hf] = v;
        }

    // epilogue: normalize, gate, store as tf32 bits (A operand of outproj)
    #pragma unroll
    for (int mi = 0; mi < 2; mi++) {
        #pragma unroll
        for (int hf = 0; hf < 2; hf++) {
            int s = wid * 32 + mi * 16 + lr + hf * 8;
            float inv = 1.0f / rsum[mi][hf];
            const float* gp = g_gate + base + (size_t)s * srow;
            float* op = g_o + base + (size_t)s * srow;
            #pragma unroll
            for (int ni2 = 0; ni2 < 4; ni2++) {
                int c = ni2 * 8 + la3 * 2;
                float2 gv = *(const float2*)(gp + c);
                float2 ov;
                ov.x = __uint_as_float(f2tf(acc2[mi][ni2][hf * 2 + 0] * inv * gv.x));
                ov.y = __uint_as_float(f2tf(acc2[mi][ni2][hf * 2 + 1] * inv * gv.y));
                *(float2*)(op + c) = ov;
            }
        }
    }
}

// ---------------- launch ----------------
extern "C" void kernel_launch(void* const* d_in, const int* in_sizes, int n_in,
                              void* d_out, int out_size) {
    const float* msa  = (const float*)d_in[0];
    const float* ln_s = (const float*)d_in[1];
    const float* ln_b = (const float*)d_in[2];
    const float* wq   = (const float*)d_in[3];
    const float* wk   = (const float*)d_in[4];
    const float* wv   = (const float*)d_in[5];
    const float* wg   = (const float*)d_in[6];
    const float* bg   = (const float*)d_in[7];
    const float* wo   = (const float*)d_in[8];
    const float* bo   = (const float*)d_in[9];
    float* out = (float*)d_out;

    cudaFuncSetAttribute(attn_tc_kernel, cudaFuncAttributeMaxDynamicSharedMemorySize, ATTN_SMEM);

    ln_kernel<<<ROWS / 8, dim3(32, 8)>>>(msa, ln_s, ln_b);
    transpose_w<<<dim3(8, 8, 5), dim3(32, 8)>>>(wq, wk, wv, wg, wo);
    proj_kernel<<<dim3(8, 512), 256>>>(bg);
    attn_tc_kernel<<<L_DIM * H_DIM, 128, ATTN_SMEM>>>();
    outproj_kernel<<<dim3(2, 512), 256>>>(bo, out);
}

// round 14
// speedup vs baseline: 1.0002x; 1.0002x over previous
#include <cuda_runtime.h>
#include <cuda_bf16.h>
#include <cstdint>
#include <cstddef>
#include <math.h>

// Problem constants
#define S_DIM 128
#define L_DIM 512
#define D_DIM 256
#define H_DIM 8
#define C_DIM 32
#define HC    256
#define ROWS  65536

// ---------------- scratch (device globals; allocation-free) ----------------
// g_x, g_q, g_k, g_v, g_wT, g_o hold tf32-bit patterns (as float storage).
__device__ float g_x[(size_t)ROWS * D_DIM];
__device__ float g_q[(size_t)ROWS * HC];
__device__ float g_k[(size_t)ROWS * HC];
__device__ float g_v[(size_t)ROWS * HC];
__device__ float g_gate[(size_t)ROWS * HC];   // fp32 (sigmoid output)
__device__ float g_o[(size_t)ROWS * HC];
__device__ float g_wT[5 * 256 * 256];         // transposed weights, tf32 bits; wq pre-scaled

__device__ __forceinline__ uint32_t f2tf(float f) {
    uint32_t u;
    asm("cvt.rna.tf32.f32 %0, %1;" : "=r"(u) : "f"(f));
    return u;
}
__device__ __forceinline__ uint32_t smem_u32(const void* p) {
    uint32_t a;
    asm("{ .reg .u64 t; cvta.to.shared.u64 t, %1; cvt.u32.u64 %0, t; }" : "=r"(a) : "l"(p));
    return a;
}
__device__ __forceinline__ void cp16(uint32_t dst, const void* src) {
    asm volatile("cp.async.cg.shared.global [%0], [%1], 16;" :: "r"(dst), "l"(src) : "memory");
}
#define CP_COMMIT() asm volatile("cp.async.commit_group;" ::: "memory")
#define CP_WAIT(n)  asm volatile("cp.async.wait_group %0;" :: "n"(n) : "memory")
__device__ __forceinline__ void ldsm4(uint32_t& r0, uint32_t& r1, uint32_t& r2, uint32_t& r3,
                                      uint32_t addr) {
    asm volatile("ldmatrix.sync.aligned.m8n8.x4.shared.b16 {%0,%1,%2,%3}, [%4];"
                 : "=r"(r0), "=r"(r1), "=r"(r2), "=r"(r3) : "r"(addr));
}
__device__ __forceinline__ void mma8(float* c, const uint32_t* a, uint32_t b0, uint32_t b1) {
    asm volatile(
        "mma.sync.aligned.m16n8k8.row.col.f32.tf32.tf32.f32 "
        "{%0,%1,%2,%3}, {%4,%5,%6,%7}, {%8,%9}, {%0,%1,%2,%3};"
        : "+f"(c[0]), "+f"(c[1]), "+f"(c[2]), "+f"(c[3])
        : "r"(a[0]), "r"(a[1]), "r"(a[2]), "r"(a[3]), "r"(b0), "r"(b1));
}

// ---------------- fused prep: LayerNorm (tf32 out) + weight transpose ----------------
__global__ void __launch_bounds__(256) prep_kernel(const float* __restrict__ in,
                                                   const float* __restrict__ sc,
                                                   const float* __restrict__ bi,
                                                   const float* __restrict__ wq,
                                                   const float* __restrict__ wk,
                                                   const float* __restrict__ wv,
                                                   const float* __restrict__ wg,
                                                   const float* __restrict__ wo) {
    __shared__ float t[32][33];
    int tx = threadIdx.x, ty = threadIdx.y;
    if (blockIdx.x < 8192) {
        // ---- LayerNorm: one warp per row ----
        int row  = blockIdx.x * 8 + ty;
        int lane = tx;
        const float4* p = (const float4*)(in + (size_t)row * D_DIM);
        float4 a = p[lane];
        float4 b = p[lane + 32];
        float s  = a.x + a.y + a.z + a.w + b.x + b.y + b.z + b.w;
        float s2 = a.x*a.x + a.y*a.y + a.z*a.z + a.w*a.w
                 + b.x*b.x + b.y*b.y + b.z*b.z + b.w*b.w;
        #pragma unroll
        for (int off = 16; off > 0; off >>= 1) {
            s  += __shfl_xor_sync(0xFFFFFFFF, s,  off);
            s2 += __shfl_xor_sync(0xFFFFFFFF, s2, off);
        }
        float mean = s * (1.0f / 256.0f);
        float var  = s2 * (1.0f / 256.0f) - mean * mean;
        float inv  = rsqrtf(var + 1e-5f);

        const float4* scp = (const float4*)sc;
        const float4* bip = (const float4*)bi;
        float4 sa = scp[lane], sb = scp[lane + 32];
        float4 ba = bip[lane], bb = bip[lane + 32];
        uint4 oa, ob;
        oa.x = f2tf((a.x - mean) * inv * sa.x + ba.x);
        oa.y = f2tf((a.y - mean) * inv * sa.y + ba.y);
        oa.z = f2tf((a.z - mean) * inv * sa.z + ba.z);
        oa.w = f2tf((a.w - mean) * inv * sa.w + ba.w);
        ob.x = f2tf((b.x - mean) * inv * sb.x + bb.x);
        ob.y = f2tf((b.y - mean) * inv * sb.y + bb.y);
        ob.z = f2tf((b.z - mean) * inv * sb.z + bb.z);
        ob.w = f2tf((b.w - mean) * inv * sb.w + bb.w);
        uint4* q = (uint4*)(g_x + (size_t)row * D_DIM);
        q[lane]      = oa;
        q[lane + 32] = ob;
    } else {
        // ---- weight transpose -> tf32 bits; wq pre-scaled by 1/sqrt(C) ----
        int b  = blockIdx.x - 8192;       // 0..319
        int bx = b & 7;
        int by = (b >> 3) & 7;
        int bz = b >> 6;                  // 0..4
        const float* srcs[5] = {wq, wk, wv, wg, wo};
        const float* src = srcs[bz];
        float* dst = g_wT + (size_t)bz * 65536;
        float mul = (bz == 0) ? 0.17677669529663687f : 1.0f;
        int x  = bx * 32 + tx;
        int y0 = by * 32;
        #pragma unroll
        for (int j = 0; j < 32; j += 8)
            t[ty + j][tx] = src[(size_t)(y0 + ty + j) * 256 + x];
        __syncthreads();
        int nx = by * 32 + tx;
        #pragma unroll
        for (int j = 0; j < 32; j += 8)
            dst[(size_t)(bx * 32 + ty + j) * 256 + nx] =
                __uint_as_float(f2tf(t[tx][ty + j] * mul));
    }
}

// ---------------- TF32 GEMM: 128x128 tile, 256 threads, 3-stage cp.async + ldmatrix ----------------
#define BKW 20
#define BUFW (128 * BKW)
#define NSTAGE 3
#define GEMM_SMEM (2 * NSTAGE * BUFW * 4)   // 61440 B

__device__ __forceinline__ void gemm_ldsm_tile(const float* __restrict__ A,
                                               const float* __restrict__ Bt,
                                               int row0, int col0,
                                               float* __restrict__ Cout, int ldc,
                                               const float* __restrict__ bias,
                                               bool do_sig, bool tf32_out) {
    extern __shared__ __align__(16) uint32_t dynsm[];
    uint32_t* As = dynsm;                   // NSTAGE * BUFW
    uint32_t* Bs = dynsm + NSTAGE * BUFW;

    int tid  = threadIdx.x;
    int lane = tid & 31;
    int wid  = tid >> 5;
    int wm   = wid & 1;
    int wn   = wid >> 1;
    int la3  = lane & 3;
    int lr   = lane >> 2;

    uint32_t sA = smem_u32(As);
    uint32_t sB = smem_u32(Bs);

    int tileid = lane >> 3;
    int lrow   = lane & 7;
    uint32_t aBase = (((uint32_t)(wm * 64 + (tileid & 1) * 8 + lrow)) * BKW
                      + (uint32_t)(tileid >> 1) * 4) * 4;
    uint32_t bBase = (((uint32_t)(wn * 32 + (tileid & 1) * 8 + lrow)) * BKW
                      + (uint32_t)(tileid >> 1) * 4) * 4;

    float acc[4][4][4];
    #pragma unroll
    for (int mi = 0; mi < 4; mi++)
        #pragma unroll
        for (int ni = 0; ni < 4; ni++)
            #pragma unroll
            for (int q = 0; q < 4; q++) acc[mi][ni][q] = 0.0f;

    int m0 = tid >> 2;                 // rows for this thread: m0, m0+64
    int kq = (tid & 3) * 4;

    const float* aRow0 = A  + (size_t)(row0 + m0) * 256 + kq;
    const float* aRow1 = A  + (size_t)(row0 + m0 + 64) * 256 + kq;
    const float* bRow0 = Bt + (size_t)(col0 + m0) * 256 + kq;
    const float* bRow1 = Bt + (size_t)(col0 + m0 + 64) * 256 + kq;
    uint32_t sa0 = sA + (uint32_t)(m0 * BKW + kq) * 4;
    uint32_t sa1 = sA + (uint32_t)((m0 + 64) * BKW + kq) * 4;
    uint32_t sb0 = sB + (uint32_t)(m0 * BKW + kq) * 4;
    uint32_t sb1 = sB + (uint32_t)((m0 + 64) * BKW + kq) * 4;

    // prologue: chunks 0 and 1 into stages 0, 1
    #pragma unroll
    for (int c = 0; c < 2; c++) {
        uint32_t off = (uint32_t)c * (BUFW * 4);
        cp16(sa0 + off, aRow0 + c * 16);
        cp16(sa1 + off, aRow1 + c * 16);
        cp16(sb0 + off, bRow0 + c * 16);
        cp16(sb1 + off, bRow1 + c * 16);
        CP_COMMIT();
    }

    int bufc = 0;   // stage holding chunk c
    int bufp = 2;   // stage to receive chunk c+2
    for (int c = 0; c < 16; c++) {
        // ensure chunk c has landed (outstanding <= 1 means chunks..c complete)
        if (c < 15) { CP_WAIT(1); } else { CP_WAIT(0); }
        __syncthreads();   // all warps past compute c-1, chunk c visible to all

        // issue chunk c+2 into bufp (last read in chunk c-1; safe after the sync)
        if (c + 2 < 16) {
            uint32_t off = (uint32_t)bufp * (BUFW * 4);
            cp16(sa0 + off, aRow0 + (c + 2) * 16);
            cp16(sa1 + off, aRow1 + (c + 2) * 16);
            cp16(sb0 + off, bRow0 + (c + 2) * 16);
            cp16(sb1 + off, bRow1 + (c + 2) * 16);
            CP_COMMIT();
        }

        uint32_t aOff = sA + (uint32_t)bufc * (BUFW * 4) + aBase;
        uint32_t bOff = sB + (uint32_t)bufc * (BUFW * 4) + bBase;
        #pragma unroll
        for (int kk = 0; kk < 16; kk += 8) {
            uint32_t af[4][4];
            #pragma unroll
            for (int mi = 0; mi < 4; mi++)
                ldsm4(af[mi][0], af[mi][1], af[mi][2], af[mi][3],
                      aOff + (uint32_t)(mi * 16 * BKW + kk) * 4);
            uint32_t bf[4][2];
            #pragma unroll
            for (int j = 0; j < 2; j++) {
                uint32_t r0, r1, r2, r3;
                ldsm4(r0, r1, r2, r3, bOff + (uint32_t)(j * 16 * BKW + kk) * 4);
                bf[2 * j + 0][0] = r0; bf[2 * j + 1][0] = r1;
                bf[2 * j + 0][1] = r2; bf[2 * j + 1][1] = r3;
            }
            #pragma unroll
            for (int mi = 0; mi < 4; mi++)
                #pragma unroll
                for (int ni = 0; ni < 4; ni++)
                    mma8(acc[mi][ni], af[mi], bf[ni][0], bf[ni][1]);
        }

        bufc = (bufc == NSTAGE - 1) ? 0 : bufc + 1;
        bufp = (bufp == NSTAGE - 1) ? 0 : bufp + 1;
    }

    #pragma unroll
    for (int mi = 0; mi < 4; mi++) {
        #pragma unroll
        for (int half = 0; half < 2; half++) {
            int rg = row0 + wm * 64 + mi * 16 + lr + half * 8;
            #pragma unroll
            for (int ni = 0; ni < 4; ni++) {
                int cg = col0 + wn * 32 + ni * 8 + la3 * 2;
                float v0 = acc[mi][ni][half * 2 + 0];
                float v1 = acc[mi][ni][half * 2 + 1];
                if (bias) { v0 += bias[cg]; v1 += bias[cg + 1]; }
                if (do_sig) {
                    v0 = 1.0f / (1.0f + __expf(-v0));
                    v1 = 1.0f / (1.0f + __expf(-v1));
                }
                if (tf32_out) {
                    v0 = __uint_as_float(f2tf(v0));
                    v1 = __uint_as_float(f2tf(v1));
                }
                *(float2*)(Cout + (size_t)rg * ldc + cg) = make_float2(v0, v1);
            }
        }
    }
}

// grid: (8, 512) — N-block fastest so CTAs sharing an A tile are concurrent
__global__ void __launch_bounds__(256, 2) proj_kernel(const float* __restrict__ bg) {
    int nblk = blockIdx.x;              // 0..7
    int row0 = blockIdx.y * 128;
    int wsel = nblk >> 1;
    int colW = (nblk & 1) * 128;
    const float* Bt = g_wT + (size_t)wsel * 65536;
    float* out;
    const float* bias = nullptr;
    bool sig = false, tf = true;
    switch (wsel) {
        case 0: out = g_q; break;
        case 1: out = g_k; break;
        case 2: out = g_v; break;
        default: out = g_gate; bias = bg; sig = true; tf = false; break;
    }
    gemm_ldsm_tile(g_x, Bt, row0, colW, out, HC, bias, sig, tf);
}

// grid: (2, 512)
__global__ void __launch_bounds__(256, 2) outproj_kernel(const float* __restrict__ bo,
                                                         float* __restrict__ out) {
    int colW = blockIdx.x * 128;
    int row0 = blockIdx.y * 128;
    gemm_ldsm_tile(g_o, g_wT + 4 * 65536, row0, colW, out, D_DIM, bo, false, false);
}

// ---------------- attention: cp.async K/V staging, Q direct from gmem (R13 proven) ----------------
#define ATW 36
#define ATTN_SMEM (2 * 128 * ATW * 4)   // 36864 B

__global__ void __launch_bounds__(128) attn_tc_kernel() {
    extern __shared__ uint32_t shm[];
    uint32_t* Ks = shm;
    uint32_t* Vs = shm + 128 * ATW;

    int l = blockIdx.x >> 3;
    int h = blockIdx.x & 7;
    int tid  = threadIdx.x;
    int lane = tid & 31;
    int wid  = tid >> 5;
    int la3  = lane & 3;
    int lr   = lane >> 2;

    const size_t srow = (size_t)L_DIM * HC;
    const size_t base = (size_t)l * HC + (size_t)h * C_DIM;

    uint32_t kA = smem_u32(Ks);
    uint32_t vA = smem_u32(Vs);

    // ---- stage K, V via cp.async ----
    {
        int tloc = tid >> 3;
        int cq   = (tid & 7) * 4;
        #pragma unroll
        for (int p = 0; p < 8; p++) {
            int r = p * 16 + tloc;
            size_t gi = base + (size_t)r * srow + cq;
            uint32_t so = (uint32_t)(r * ATW + cq) * 4;
            cp16(kA + so, g_k + gi);
            cp16(vA + so, g_v + gi);
        }
    }
    CP_COMMIT();

    // ---- Q fragments straight from gmem (tf32 bits, pre-scaled) ----
    uint32_t af1[4][2][4];
    {
        const uint32_t* qg = (const uint32_t*)g_q;
        #pragma unroll
        for (int mi = 0; mi < 2; mi++) {
            int r = wid * 32 + mi * 16 + lr;
            const uint32_t* q0 = qg + base + (size_t)r * srow;
            const uint32_t* q8 = qg + base + (size_t)(r + 8) * srow;
            #pragma unroll
            for (int kk = 0; kk < 4; kk++) {
                int c = kk * 8 + la3;
                af1[kk][mi][0] = q0[c];
                af1[kk][mi][1] = q8[c];
                af1[kk][mi][2] = q0[c + 4];
                af1[kk][mi][3] = q8[c + 4];
            }
        }
    }

    CP_WAIT(0);
    __syncthreads();

    float acc2[2][4][4];
    #pragma unroll
    for (int mi = 0; mi < 2; mi++)
        #pragma unroll
        for (int ni = 0; ni < 4; ni++)
            #pragma unroll
            for (int q = 0; q < 4; q++) acc2[mi][ni][q] = 0.0f;
    float rsum[2][2] = {{0.f, 0.f}, {0.f, 0.f}};

    int srcA = (lane & 28) | (la3 >> 1);
    int srcB = srcA | 2;
    int sel  = la3 & 1;

    for (int ni = 0; ni < 16; ni++) {
        float s[2][4];
        #pragma unroll
        for (int mi = 0; mi < 2; mi++)
            #pragma unroll
            for (int q = 0; q < 4; q++) s[mi][q] = 0.0f;

        #pragma unroll
        for (int kk = 0; kk < 4; kk++) {
            int t = ni * 8 + lr;
            int c = kk * 8 + la3;
            uint32_t b0 = Ks[t * ATW + c];
            uint32_t b1 = Ks[t * ATW + c + 4];
            mma8(s[0], af1[kk][0], b0, b1);
            mma8(s[1], af1[kk][1], b0, b1);
        }

        float e[2][4];
        #pragma unroll
        for (int mi = 0; mi < 2; mi++)
            #pragma unroll
            for (int q = 0; q < 4; q++) {
                float ev = __expf(s[mi][q]);
                e[mi][q] = ev;
                rsum[mi][q >> 1] += ev;
            }

        uint32_t a2[2][4];
        #pragma unroll
        for (int mi = 0; mi < 2; mi++) {
            float v0 = __shfl_sync(0xFFFFFFFF, e[mi][0], srcA);
            float v1 = __shfl_sync(0xFFFFFFFF, e[mi][1], srcA);
            float v2 = __shfl_sync(0xFFFFFFFF, e[mi][2], srcA);
            float v3 = __shfl_sync(0xFFFFFFFF, e[mi][3], srcA);
            float w0 = __shfl_sync(0xFFFFFFFF, e[mi][0], srcB);
            float w1 = __shfl_sync(0xFFFFFFFF, e[mi][1], srcB);
            float w2 = __shfl_sync(0xFFFFFFFF, e[mi][2], srcB);
            float w3 = __shfl_sync(0xFFFFFFFF, e[mi][3], srcB);
            a2[mi][0] = f2tf(sel ? v1 : v0);
            a2[mi][1] = f2tf(sel ? v3 : v2);
            a2[mi][2] = f2tf(sel ? w1 : w0);
            a2[mi][3] = f2tf(sel ? w3 : w2);
        }

        #pragma unroll
        for (int ni2 = 0; ni2 < 4; ni2++) {
            int t = ni * 8 + la3;
            uint32_t b0 = Vs[t * ATW + ni2 * 8 + lr];
            uint32_t b1 = Vs[(t + 4) * ATW + ni2 * 8 + lr];
            mma8(acc2[0][ni2], a2[0], b0, b1);
            mma8(acc2[1][ni2], a2[1], b0, b1);
        }
    }

    #pragma unroll
    for (int mi = 0; mi < 2; mi++)
        #pragma unroll
        for (int hf = 0; hf < 2; hf++) {
            float v = rsum[mi][hf];
            v += __shfl_xor_sync(0xFFFFFFFF, v, 1);
            v += __shfl_xor_sync(0xFFFFFFFF, v, 2);
            rsum[mi][hf] = v;
        }

    // epilogue: normalize, gate, store as tf32 bits (A operand of outproj)
    #pragma unroll
    for (int mi = 0; mi < 2; mi++) {
        #pragma unroll
        for (int hf = 0; hf < 2; hf++) {
            int s = wid * 32 + mi * 16 + lr + hf * 8;
            float inv = 1.0f / rsum[mi][hf];
            const float* gp = g_gate + base + (size_t)s * srow;
            float* op = g_o + base + (size_t)s * srow;
            #pragma unroll
            for (int ni2 = 0; ni2 < 4; ni2++) {
                int c = ni2 * 8 + la3 * 2;
                float2 gv = *(const float2*)(gp + c);
                float2 ov;
                ov.x = __uint_as_float(f2tf(acc2[mi][ni2][hf * 2 + 0] * inv * gv.x));
                ov.y = __uint_as_float(f2tf(acc2[mi][ni2][hf * 2 + 1] * inv * gv.y));
                *(float2*)(op + c) = ov;
            }
        }
    }
}

// ---------------- launch ----------------
extern "C" void kernel_launch(void* const* d_in, const int* in_sizes, int n_in,
                              void* d_out, int out_size) {
    const float* msa  = (const float*)d_in[0];
    const float* ln_s = (const float*)d_in[1];
    const float* ln_b = (const float*)d_in[2];
    const float* wq   = (const float*)d_in[3];
    const float* wk   = (const float*)d_in[4];
    const float* wv   = (const float*)d_in[5];
    const float* wg   = (const float*)d_in[6];
    const float* bg   = (const float*)d_in[7];
    const float* wo   = (const float*)d_in[8];
    const float* bo   = (const float*)d_in[9];
    float* out = (float*)d_out;

    cudaFuncSetAttribute(attn_tc_kernel,  cudaFuncAttributeMaxDynamicSharedMemorySize, ATTN_SMEM);
    cudaFuncSetAttribute(proj_kernel,     cudaFuncAttributeMaxDynamicSharedMemorySize, GEMM_SMEM);
    cudaFuncSetAttribute(outproj_kernel,  cudaFuncAttributeMaxDynamicSharedMemorySize, GEMM_SMEM);

    prep_kernel<<<8192 + 320, dim3(32, 8)>>>(msa, ln_s, ln_b, wq, wk, wv, wg, wo);
    proj_kernel<<<dim3(8, 512), 256, GEMM_SMEM>>>(bg);
    attn_tc_kernel<<<L_DIM * H_DIM, 128, ATTN_SMEM>>>();
    outproj_kernel<<<dim3(2, 512), 256, GEMM_SMEM>>>(bo, out);
}

// round 15
// speedup vs baseline: 1.2669x; 1.2666x over previous
#include <cuda_runtime.h>
#include <cuda_bf16.h>
#include <cstdint>
#include <cstddef>
#include <math.h>

// Problem constants
#define S_DIM 128
#define L_DIM 512
#define D_DIM 256
#define H_DIM 8
#define C_DIM 32
#define HC    256
#define ROWS  65536

// ---------------- scratch (device globals; allocation-free) ----------------
// g_x, g_wT, g_o hold tf32-bit patterns (as float storage).
__device__ float g_x[(size_t)ROWS * D_DIM];
__device__ float g_o[(size_t)ROWS * HC];
__device__ float g_wT[5 * 256 * 256];     // transposed weights, tf32 bits; wq pre-scaled

__device__ __forceinline__ uint32_t f2tf(float f) {
    uint32_t u;
    asm("cvt.rna.tf32.f32 %0, %1;" : "=r"(u) : "f"(f));
    return u;
}
__device__ __forceinline__ uint32_t smem_u32(const void* p) {
    uint32_t a;
    asm("{ .reg .u64 t; cvta.to.shared.u64 t, %1; cvt.u32.u64 %0, t; }" : "=r"(a) : "l"(p));
    return a;
}
__device__ __forceinline__ void cp16(uint32_t dst, const void* src) {
    asm volatile("cp.async.cg.shared.global [%0], [%1], 16;" :: "r"(dst), "l"(src) : "memory");
}
#define CP_COMMIT() asm volatile("cp.async.commit_group;" ::: "memory")
#define CP_WAIT(n)  asm volatile("cp.async.wait_group %0;" :: "n"(n) : "memory")
__device__ __forceinline__ void ldsm4(uint32_t& r0, uint32_t& r1, uint32_t& r2, uint32_t& r3,
                                      uint32_t addr) {
    asm volatile("ldmatrix.sync.aligned.m8n8.x4.shared.b16 {%0,%1,%2,%3}, [%4];"
                 : "=r"(r0), "=r"(r1), "=r"(r2), "=r"(r3) : "r"(addr));
}
__device__ __forceinline__ void mma8(float* c, const uint32_t* a, uint32_t b0, uint32_t b1) {
    asm volatile(
        "mma.sync.aligned.m16n8k8.row.col.f32.tf32.tf32.f32 "
        "{%0,%1,%2,%3}, {%4,%5,%6,%7}, {%8,%9}, {%0,%1,%2,%3};"
        : "+f"(c[0]), "+f"(c[1]), "+f"(c[2]), "+f"(c[3])
        : "r"(a[0]), "r"(a[1]), "r"(a[2]), "r"(a[3]), "r"(b0), "r"(b1));
}

// ---------------- fused prep: LayerNorm (tf32 out) + weight transpose ----------------
__global__ void __launch_bounds__(256) prep_kernel(const float* __restrict__ in,
                                                   const float* __restrict__ sc,
                                                   const float* __restrict__ bi,
                                                   const float* __restrict__ wq,
                                                   const float* __restrict__ wk,
                                                   const float* __restrict__ wv,
                                                   const float* __restrict__ wg,
                                                   const float* __restrict__ wo) {
    __shared__ float t[32][33];
    int tx = threadIdx.x, ty = threadIdx.y;
    if (blockIdx.x < 8192) {
        int row  = blockIdx.x * 8 + ty;
        int lane = tx;
        const float4* p = (const float4*)(in + (size_t)row * D_DIM);
        float4 a = p[lane];
        float4 b = p[lane + 32];
        float s  = a.x + a.y + a.z + a.w + b.x + b.y + b.z + b.w;
        float s2 = a.x*a.x + a.y*a.y + a.z*a.z + a.w*a.w
                 + b.x*b.x + b.y*b.y + b.z*b.z + b.w*b.w;
        #pragma unroll
        for (int off = 16; off > 0; off >>= 1) {
            s  += __shfl_xor_sync(0xFFFFFFFF, s,  off);
            s2 += __shfl_xor_sync(0xFFFFFFFF, s2, off);
        }
        float mean = s * (1.0f / 256.0f);
        float var  = s2 * (1.0f / 256.0f) - mean * mean;
        float inv  = rsqrtf(var + 1e-5f);

        const float4* scp = (const float4*)sc;
        const float4* bip = (const float4*)bi;
        float4 sa = scp[lane], sb = scp[lane + 32];
        float4 ba = bip[lane], bb = bip[lane + 32];
        uint4 oa, ob;
        oa.x = f2tf((a.x - mean) * inv * sa.x + ba.x);
        oa.y = f2tf((a.y - mean) * inv * sa.y + ba.y);
        oa.z = f2tf((a.z - mean) * inv * sa.z + ba.z);
        oa.w = f2tf((a.w - mean) * inv * sa.w + ba.w);
        ob.x = f2tf((b.x - mean) * inv * sb.x + bb.x);
        ob.y = f2tf((b.y - mean) * inv * sb.y + bb.y);
        ob.z = f2tf((b.z - mean) * inv * sb.z + bb.z);
        ob.w = f2tf((b.w - mean) * inv * sb.w + bb.w);
        uint4* q = (uint4*)(g_x + (size_t)row * D_DIM);
        q[lane]      = oa;
        q[lane + 32] = ob;
    } else {
        int b  = blockIdx.x - 8192;       // 0..319
        int bx = b & 7;
        int by = (b >> 3) & 7;
        int bz = b >> 6;                  // 0..4
        const float* srcs[5] = {wq, wk, wv, wg, wo};
        const float* src = srcs[bz];
        float* dst = g_wT + (size_t)bz * 65536;
        float mul = (bz == 0) ? 0.17677669529663687f : 1.0f;
        int x  = bx * 32 + tx;
        int y0 = by * 32;
        #pragma unroll
        for (int j = 0; j < 32; j += 8)
            t[ty + j][tx] = src[(size_t)(y0 + ty + j) * 256 + x];
        __syncthreads();
        int nx = by * 32 + tx;
        #pragma unroll
        for (int j = 0; j < 32; j += 8)
            dst[(size_t)(bx * 32 + ty + j) * 256 + nx] =
                __uint_as_float(f2tf(t[tx][ty + j] * mul));
    }
}

// ---------------- fused projections + attention, one CTA per (l, h) ----------------
// 256 threads = 8 warps, warp w owns S-rows [w*16, w*16+16).
// Phase A: Q/K/V/G = X_l @ W_h (4 GEMMs 128x32xK256, cp.async double-buffered).
// Phase B: sigmoid gate (regs), K/V -> smem (tf32), Q c-frag -> A-frag via shuffle,
//          then the R13 attention loop and gated epilogue.
#define STGW 9216                     // words per stage: Xs 128*36 + Ws 4*32*36
#define FUSED_SMEM (2 * STGW * 4)     // 73728 B

__global__ void __launch_bounds__(256, 2) fused_attn_kernel(const float* __restrict__ bg) {
    extern __shared__ uint32_t shm[];
    int h = blockIdx.x;
    int l = blockIdx.y;
    int tid  = threadIdx.x;
    int lane = tid & 31;
    int wid  = tid >> 5;              // 0..7
    int la3  = lane & 3;
    int lr   = lane >> 2;

    uint32_t sbase = smem_u32(shm);
    const float* Xb = g_x + (size_t)l * 256;              // + s*131072 + k
    const float* Wb = g_wT + (size_t)h * 32 * 256;        // + z*65536 + n*256 + k

    float acc[4][4][4];               // [z][ni][q], z: 0=q 1=k 2=v 3=g
    #pragma unroll
    for (int z = 0; z < 4; z++)
        #pragma unroll
        for (int ni = 0; ni < 4; ni++)
            #pragma unroll
            for (int q = 0; q < 4; q++) acc[z][ni][q] = 0.0f;

    int tileid = lane >> 3;
    int lrow   = lane & 7;

    // ---- phase A: K-chunked GEMMs ----
    // stage chunk kc into buffer buf
    #define STAGE_CHUNK(kc, buf) do {                                                  \
        uint32_t xo = sbase + (uint32_t)(buf) * (STGW * 4);                            \
        uint32_t wo = xo + 4608 * 4;                                                   \
        _Pragma("unroll")                                                              \
        for (int i = 0; i < 4; i++) {                                                  \
            int idx = tid + i * 256;                                                   \
            int r = idx >> 3, c16 = idx & 7;                                           \
            cp16(xo + (uint32_t)(r * 36 + c16 * 4) * 4,                                \
                 Xb + (size_t)r * 131072 + (kc) * 32 + c16 * 4);                       \
            int z = idx >> 8, rw = (idx >> 3) & 31;                                    \
            cp16(wo + (uint32_t)((z * 32 + rw) * 36 + c16 * 4) * 4,                    \
                 Wb + (size_t)z * 65536 + (size_t)rw * 256 + (kc) * 32 + c16 * 4);     \
        }                                                                              \
    } while (0)

    STAGE_CHUNK(0, 0);
    CP_COMMIT();

    for (int kc = 0; kc < 8; kc++) {
        if (kc < 7) {
            STAGE_CHUNK(kc + 1, (kc + 1) & 1);
            CP_COMMIT();
            CP_WAIT(1);
        } else {
            CP_WAIT(0);
        }
        __syncthreads();

        uint32_t xo = sbase + (uint32_t)(kc & 1) * (STGW * 4);
        uint32_t wo = xo + 4608 * 4;
        uint32_t aAddr = xo + (uint32_t)((wid * 16 + (tileid & 1) * 8 + lrow) * 36
                                         + (tileid >> 1) * 4) * 4;
        uint32_t af[4][4];
        #pragma unroll
        for (int kk2 = 0; kk2 < 4; kk2++)
            ldsm4(af[kk2][0], af[kk2][1], af[kk2][2], af[kk2][3], aAddr + kk2 * 32);

        #pragma unroll
        for (int z = 0; z < 4; z++) {
            uint32_t bAddr = wo + (uint32_t)((z * 32 + (tileid & 1) * 8 + lrow) * 36
                                             + (tileid >> 1) * 4) * 4;
            #pragma unroll
            for (int kk2 = 0; kk2 < 4; kk2++) {
                uint32_t r0, r1, r2, r3, s0, s1, s2, s3;
                ldsm4(r0, r1, r2, r3, bAddr + kk2 * 32);
                ldsm4(s0, s1, s2, s3, bAddr + (16 * 36) * 4 + kk2 * 32);
                mma8(acc[z][0], af[kk2], r0, r2);
                mma8(acc[z][1], af[kk2], r1, r3);
                mma8(acc[z][2], af[kk2], s0, s2);
                mma8(acc[z][3], af[kk2], s1, s3);
            }
        }
        __syncthreads();
    }

    // ---- phase B prep ----
    // gate: sigmoid(G + bg) in registers (c-frag layout)
    #pragma unroll
    for (int ni = 0; ni < 4; ni++) {
        float b0 = bg[h * 32 + ni * 8 + la3 * 2];
        float b1 = bg[h * 32 + ni * 8 + la3 * 2 + 1];
        #pragma unroll
        for (int q = 0; q < 4; q++) {
            float v = acc[3][ni][q] + ((q & 1) ? b1 : b0);
            acc[3][ni][q] = 1.0f / (1.0f + __expf(-v));
        }
    }

    // K, V -> smem [t][36] as tf32 bits (aliases stage buffer 0)
    uint32_t* Ks = shm;
    uint32_t* Vs = shm + 4608;
    #pragma unroll
    for (int hf = 0; hf < 2; hf++) {
        int row = wid * 16 + lr + hf * 8;
        #pragma unroll
        for (int ni = 0; ni < 4; ni++) {
            int col = ni * 8 + la3 * 2;
            uint2 kv, vv;
            kv.x = f2tf(acc[1][ni][hf * 2 + 0]);
            kv.y = f2tf(acc[1][ni][hf * 2 + 1]);
            vv.x = f2tf(acc[2][ni][hf * 2 + 0]);
            vv.y = f2tf(acc[2][ni][hf * 2 + 1]);
            *(uint2*)&Ks[row * 36 + col] = kv;
            *(uint2*)&Vs[row * 36 + col] = vv;
        }
    }

    // Q: c-frag -> A-frag via quad shuffle (wq pre-scaled by 1/sqrt(C))
    int srcA = (lane & 28) | (la3 >> 1);
    int srcB = srcA | 2;
    int sel  = la3 & 1;
    uint32_t af1[4][4];
    #pragma unroll
    for (int ni = 0; ni < 4; ni++) {
        float v0 = __shfl_sync(0xFFFFFFFF, acc[0][ni][0], srcA);
        float v1 = __shfl_sync(0xFFFFFFFF, acc[0][ni][1], srcA);
        float v2 = __shfl_sync(0xFFFFFFFF, acc[0][ni][2], srcA);
        float v3 = __shfl_sync(0xFFFFFFFF, acc[0][ni][3], srcA);
        float w0 = __shfl_sync(0xFFFFFFFF, acc[0][ni][0], srcB);
        float w1 = __shfl_sync(0xFFFFFFFF, acc[0][ni][1], srcB);
        float w2 = __shfl_sync(0xFFFFFFFF, acc[0][ni][2], srcB);
        float w3 = __shfl_sync(0xFFFFFFFF, acc[0][ni][3], srcB);
        af1[ni][0] = f2tf(sel ? v1 : v0);
        af1[ni][1] = f2tf(sel ? v3 : v2);
        af1[ni][2] = f2tf(sel ? w1 : w0);
        af1[ni][3] = f2tf(sel ? w3 : w2);
    }
    __syncthreads();

    // ---- phase B: attention (R13 structure, mi collapsed to 1) ----
    float acc2[4][4];
    #pragma unroll
    for (int ni = 0; ni < 4; ni++)
        #pragma unroll
        for (int q = 0; q < 4; q++) acc2[ni][q] = 0.0f;
    float rsum[2] = {0.f, 0.f};

    for (int no = 0; no < 16; no++) {
        float s[4] = {0.f, 0.f, 0.f, 0.f};
        #pragma unroll
        for (int kk = 0; kk < 4; kk++) {
            int t = no * 8 + lr;
            int c = kk * 8 + la3;
            uint32_t b0 = Ks[t * 36 + c];
            uint32_t b1 = Ks[t * 36 + c + 4];
            mma8(s, af1[kk], b0, b1);
        }
        float e[4];
        #pragma unroll
        for (int q = 0; q < 4; q++) {
            e[q] = __expf(s[q]);
            rsum[q >> 1] += e[q];
        }
        uint32_t a2[4];
        {
            float v0 = __shfl_sync(0xFFFFFFFF, e[0], srcA);
            float v1 = __shfl_sync(0xFFFFFFFF, e[1], srcA);
            float v2 = __shfl_sync(0xFFFFFFFF, e[2], srcA);
            float v3 = __shfl_sync(0xFFFFFFFF, e[3], srcA);
            float w0 = __shfl_sync(0xFFFFFFFF, e[0], srcB);
            float w1 = __shfl_sync(0xFFFFFFFF, e[1], srcB);
            float w2 = __shfl_sync(0xFFFFFFFF, e[2], srcB);
            float w3 = __shfl_sync(0xFFFFFFFF, e[3], srcB);
            a2[0] = f2tf(sel ? v1 : v0);
            a2[1] = f2tf(sel ? v3 : v2);
            a2[2] = f2tf(sel ? w1 : w0);
            a2[3] = f2tf(sel ? w3 : w2);
        }
        #pragma unroll
        for (int ni2 = 0; ni2 < 4; ni2++) {
            int t = no * 8 + la3;
            uint32_t b0 = Vs[t * 36 + ni2 * 8 + lr];
            uint32_t b1 = Vs[(t + 4) * 36 + ni2 * 8 + lr];
            mma8(acc2[ni2], a2, b0, b1);
        }
    }

    #pragma unroll
    for (int hf = 0; hf < 2; hf++) {
        float v = rsum[hf];
        v += __shfl_xor_sync(0xFFFFFFFF, v, 1);
        v += __shfl_xor_sync(0xFFFFFFFF, v, 2);
        rsum[hf] = v;
    }

    // epilogue: normalize, gate, store o as tf32 bits
    #pragma unroll
    for (int hf = 0; hf < 2; hf++) {
        int s = wid * 16 + lr + hf * 8;
        float inv = 1.0f / rsum[hf];
        float* op = g_o + (size_t)(s * 512 + l) * 256 + h * 32;
        #pragma unroll
        for (int ni2 = 0; ni2 < 4; ni2++) {
            int c = ni2 * 8 + la3 * 2;
            float2 ov;
            ov.x = __uint_as_float(f2tf(acc2[ni2][hf * 2 + 0] * inv * acc[3][ni2][hf * 2 + 0]));
            ov.y = __uint_as_float(f2tf(acc2[ni2][hf * 2 + 1] * inv * acc[3][ni2][hf * 2 + 1]));
            *(float2*)(op + c) = ov;
        }
    }
}

// ---------------- TF32 GEMM for outproj: 128x128 tile, 3-stage cp.async + ldmatrix ----------------
#define BKW 20
#define BUFW (128 * BKW)
#define NSTAGE 3
#define GEMM_SMEM (2 * NSTAGE * BUFW * 4)

__global__ void __launch_bounds__(256, 2) outproj_kernel(const float* __restrict__ bo,
                                                         float* __restrict__ out) {
    extern __shared__ __align__(16) uint32_t dynsm[];
    uint32_t* As = dynsm;
    uint32_t* Bs = dynsm + NSTAGE * BUFW;

    int colW = blockIdx.x * 128;
    int row0 = blockIdx.y * 128;
    const float* A  = g_o;
    const float* Bt = g_wT + 4 * 65536;

    int tid  = threadIdx.x;
    int lane = tid & 31;
    int wid  = tid >> 5;
    int wm   = wid & 1;
    int wn   = wid >> 1;
    int la3  = lane & 3;
    int lr   = lane >> 2;

    uint32_t sA = smem_u32(As);
    uint32_t sB = smem_u32(Bs);

    int tileid = lane >> 3;
    int lrow   = lane & 7;
    uint32_t aBase = (((uint32_t)(wm * 64 + (tileid & 1) * 8 + lrow)) * BKW
                      + (uint32_t)(tileid >> 1) * 4) * 4;
    uint32_t bBase = (((uint32_t)(wn * 32 + (tileid & 1) * 8 + lrow)) * BKW
                      + (uint32_t)(tileid >> 1) * 4) * 4;

    float acc[4][4][4];
    #pragma unroll
    for (int mi = 0; mi < 4; mi++)
        #pragma unroll
        for (int ni = 0; ni < 4; ni++)
            #pragma unroll
            for (int q = 0; q < 4; q++) acc[mi][ni][q] = 0.0f;

    int m0 = tid >> 2;
    int kq = (tid & 3) * 4;

    const float* aRow0 = A  + (size_t)(row0 + m0) * 256 + kq;
    const float* aRow1 = A  + (size_t)(row0 + m0 + 64) * 256 + kq;
    const float* bRow0 = Bt + (size_t)(colW + m0) * 256 + kq;
    const float* bRow1 = Bt + (size_t)(colW + m0 + 64) * 256 + kq;
    uint32_t sa0 = sA + (uint32_t)(m0 * BKW + kq) * 4;
    uint32_t sa1 = sA + (uint32_t)((m0 + 64) * BKW + kq) * 4;
    uint32_t sb0 = sB + (uint32_t)(m0 * BKW + kq) * 4;
    uint32_t sb1 = sB + (uint32_t)((m0 + 64) * BKW + kq) * 4;

    #pragma unroll
    for (int c = 0; c < 2; c++) {
        uint32_t off = (uint32_t)c * (BUFW * 4);
        cp16(sa0 + off, aRow0 + c * 16);
        cp16(sa1 + off, aRow1 + c * 16);
        cp16(sb0 + off, bRow0 + c * 16);
        cp16(sb1 + off, bRow1 + c * 16);
        CP_COMMIT();
    }

    int bufc = 0, bufp = 2;
    for (int c = 0; c < 16; c++) {
        if (c < 15) { CP_WAIT(1); } else { CP_WAIT(0); }
        __syncthreads();

        if (c + 2 < 16) {
            uint32_t off = (uint32_t)bufp * (BUFW * 4);
            cp16(sa0 + off, aRow0 + (c + 2) * 16);
            cp16(sa1 + off, aRow1 + (c + 2) * 16);
            cp16(sb0 + off, bRow0 + (c + 2) * 16);
            cp16(sb1 + off, bRow1 + (c + 2) * 16);
            CP_COMMIT();
        }

        uint32_t aOff = sA + (uint32_t)bufc * (BUFW * 4) + aBase;
        uint32_t bOff = sB + (uint32_t)bufc * (BUFW * 4) + bBase;
        #pragma unroll
        for (int kk = 0; kk < 16; kk += 8) {
            uint32_t af[4][4];
            #pragma unroll
            for (int mi = 0; mi < 4; mi++)
                ldsm4(af[mi][0], af[mi][1], af[mi][2], af[mi][3],
                      aOff + (uint32_t)(mi * 16 * BKW + kk) * 4);
            uint32_t bf[4][2];
            #pragma unroll
            for (int j = 0; j < 2; j++) {
                uint32_t r0, r1, r2, r3;
                ldsm4(r0, r1, r2, r3, bOff + (uint32_t)(j * 16 * BKW + kk) * 4);
                bf[2 * j + 0][0] = r0; bf[2 * j + 1][0] = r1;
                bf[2 * j + 0][1] = r2; bf[2 * j + 1][1] = r3;
            }
            #pragma unroll
            for (int mi = 0; mi < 4; mi++)
                #pragma unroll
                for (int ni = 0; ni < 4; ni++)
                    mma8(acc[mi][ni], af[mi], bf[ni][0], bf[ni][1]);
        }

        bufc = (bufc == NSTAGE - 1) ? 0 : bufc + 1;
        bufp = (bufp == NSTAGE - 1) ? 0 : bufp + 1;
    }

    #pragma unroll
    for (int mi = 0; mi < 4; mi++) {
        #pragma unroll
        for (int half = 0; half < 2; half++) {
            int rg = row0 + wm * 64 + mi * 16 + lr + half * 8;
            #pragma unroll
            for (int ni = 0; ni < 4; ni++) {
                int cg = colW + wn * 32 + ni * 8 + la3 * 2;
                float v0 = acc[mi][ni][half * 2 + 0] + bo[cg];
                float v1 = acc[mi][ni][half * 2 + 1] + bo[cg + 1];
                *(float2*)(out + (size_t)rg * 256 + cg) = make_float2(v0, v1);
            }
        }
    }
}

// ---------------- launch ----------------
extern "C" void kernel_launch(void* const* d_in, const int* in_sizes, int n_in,
                              void* d_out, int out_size) {
    const float* msa  = (const float*)d_in[0];
    const float* ln_s = (const float*)d_in[1];
    const float* ln_b = (const float*)d_in[2];
    const float* wq   = (const float*)d_in[3];
    const float* wk   = (const float*)d_in[4];
    const float* wv   = (const float*)d_in[5];
    const float* wg   = (const float*)d_in[6];
    const float* bg   = (const float*)d_in[7];
    const float* wo   = (const float*)d_in[8];
    const float* bo   = (const float*)d_in[9];
    float* out = (float*)d_out;

    cudaFuncSetAttribute(fused_attn_kernel, cudaFuncAttributeMaxDynamicSharedMemorySize, FUSED_SMEM);
    cudaFuncSetAttribute(outproj_kernel,    cudaFuncAttributeMaxDynamicSharedMemorySize, GEMM_SMEM);

    prep_kernel<<<8192 + 320, dim3(32, 8)>>>(msa, ln_s, ln_b, wq, wk, wv, wg, wo);
    fused_attn_kernel<<<dim3(H_DIM, L_DIM), 256, FUSED_SMEM>>>(bg);
    outproj_kernel<<<dim3(2, 512), 256, GEMM_SMEM>>>(bo, out);
}